// round 3
// baseline (speedup 1.0000x reference)
#include <cuda_runtime.h>

// ---------------------------------------------------------------------------
// Problem constants
// ---------------------------------------------------------------------------
constexpr int Bn   = 128;          // batch
constexpr int Tn   = 128;          // seq len
constexpr int Cn   = 256;          // embed dim
constexpr int Hn   = 4;            // heads
constexpr int Ln   = 6;            // layers
constexpr int Vn   = 10000;        // vocab
constexpr int HSn  = 64;           // head size
constexpr int DFFn = 1024;         // ffn hidden
constexpr int NTOK = Bn * Tn;      // 16384 tokens

// ---------------------------------------------------------------------------
// Scratch (device globals -- allocation-free per harness rules)
// ---------------------------------------------------------------------------
__device__ float g_x  [NTOK * Cn];
__device__ float g_h  [NTOK * Cn];
__device__ float g_q  [NTOK * Cn];
__device__ float g_k  [NTOK * Cn];
__device__ float g_v  [NTOK * Cn];
__device__ float g_att[NTOK * Cn];
__device__ float g_ffn[NTOK * DFFn];

// ---------------------------------------------------------------------------
// Embedding: x[b,t,:] = tok_emb[idx[b,t],:] + pos_emb[t,:]
// ---------------------------------------------------------------------------
__global__ void embed_kernel(const int* __restrict__ idx,
                             const float* __restrict__ tok,
                             const float* __restrict__ pos) {
    int token = blockIdx.x;
    int c     = threadIdx.x;
    int t     = token % Tn;
    int id    = idx[token];
    g_x[token * Cn + c] = tok[id * Cn + c] + pos[t * Cn + c];
}

// ---------------------------------------------------------------------------
// LayerNorm over C=256, one block per token, one thread per channel
// ---------------------------------------------------------------------------
__global__ void ln_kernel(const float* __restrict__ in,
                          const float* __restrict__ gg,
                          const float* __restrict__ bb,
                          float* __restrict__ out) {
    __shared__ float red[Cn];
    int token = blockIdx.x;
    int c     = threadIdx.x;
    float v   = in[token * Cn + c];

    red[c] = v;
    __syncthreads();
    #pragma unroll
    for (int s = Cn / 2; s > 0; s >>= 1) {
        if (c < s) red[c] += red[c + s];
        __syncthreads();
    }
    float mean = red[0] * (1.0f / Cn);
    __syncthreads();

    float d = v - mean;
    red[c] = d * d;
    __syncthreads();
    #pragma unroll
    for (int s = Cn / 2; s > 0; s >>= 1) {
        if (c < s) red[c] += red[c + s];
        __syncthreads();
    }
    float var = red[0] * (1.0f / Cn);

    out[token * Cn + c] = d * rsqrtf(var + 1e-5f) * gg[c] + bb[c];
}

// ---------------------------------------------------------------------------
// SGEMM: C[M,N] = A[M,K] @ B[K,N]  (row-major), fused epilogues.
//   EPI 0: plain store
//   EPI 1: + bias
//   EPI 2: + bias, relu
//   EPI 3: + bias + residual (res has same layout as C)
// Tile: 128x64, BK=16, 256 threads, 8x4 micro-tile per thread.
// ---------------------------------------------------------------------------
constexpr int GBM = 128;
constexpr int GBN = 64;
constexpr int GBK = 16;
constexpr int GTM = 8;
constexpr int GTN = 4;

template <int EPI>
__global__ void __launch_bounds__(256)
sgemm_kernel(const float* __restrict__ A, const float* __restrict__ B,
             const float* __restrict__ bias, const float* __restrict__ res,
             float* __restrict__ C, int M, int N, int K) {
    __shared__ __align__(16) float As[GBK][GBM];
    __shared__ __align__(16) float Bs[GBK][GBN];

    const int tid = threadIdx.x;
    const int bx  = blockIdx.x;
    const int by  = blockIdx.y;
    const int tx  = tid & 15;          // 0..15  -> N dir
    const int ty  = tid >> 4;          // 0..15  -> M dir
    const int rowBase = by * GBM;
    const int colBase = bx * GBN;

    float acc[GTM][GTN];
    #pragma unroll
    for (int i = 0; i < GTM; i++)
        #pragma unroll
        for (int j = 0; j < GTN; j++) acc[i][j] = 0.0f;

    for (int k0 = 0; k0 < K; k0 += GBK) {
        // --- load A tile (128x16) : 512 float4, 2 per thread, store transposed
        #pragma unroll
        for (int it = 0; it < 2; it++) {
            int f   = tid + it * 256;
            int ar  = f >> 2;          // 0..127
            int ac4 = f & 3;           // which float4 within row
            float4 av = *reinterpret_cast<const float4*>(
                &A[(size_t)(rowBase + ar) * K + k0 + ac4 * 4]);
            As[ac4 * 4 + 0][ar] = av.x;
            As[ac4 * 4 + 1][ar] = av.y;
            As[ac4 * 4 + 2][ar] = av.z;
            As[ac4 * 4 + 3][ar] = av.w;
        }
        // --- load B tile (16x64) : 256 float4, 1 per thread
        {
            int br   = tid >> 4;       // 0..15
            int bc4  = tid & 15;       // 0..15
            int gcol = colBase + bc4 * 4;
            float4 bv;
            if (gcol + 3 < N) {
                bv = *reinterpret_cast<const float4*>(
                    &B[(size_t)(k0 + br) * N + gcol]);
            } else {
                bv.x = (gcol + 0 < N) ? B[(size_t)(k0 + br) * N + gcol + 0] : 0.f;
                bv.y = (gcol + 1 < N) ? B[(size_t)(k0 + br) * N + gcol + 1] : 0.f;
                bv.z = (gcol + 2 < N) ? B[(size_t)(k0 + br) * N + gcol + 2] : 0.f;
                bv.w = (gcol + 3 < N) ? B[(size_t)(k0 + br) * N + gcol + 3] : 0.f;
            }
            *reinterpret_cast<float4*>(&Bs[br][bc4 * 4]) = bv;
        }
        __syncthreads();

        #pragma unroll
        for (int k = 0; k < GBK; k++) {
            float ra[GTM], rb[GTN];
            #pragma unroll
            for (int i = 0; i < GTM; i++) ra[i] = As[k][ty * GTM + i];
            #pragma unroll
            for (int j = 0; j < GTN; j++) rb[j] = Bs[k][tx * GTN + j];
            #pragma unroll
            for (int i = 0; i < GTM; i++)
                #pragma unroll
                for (int j = 0; j < GTN; j++)
                    acc[i][j] = fmaf(ra[i], rb[j], acc[i][j]);
        }
        __syncthreads();
    }

    // --- epilogue
    #pragma unroll
    for (int i = 0; i < GTM; i++) {
        int row = rowBase + ty * GTM + i;
        #pragma unroll
        for (int j = 0; j < GTN; j++) {
            int col = colBase + tx * GTN + j;
            if (col < N) {
                float v = acc[i][j];
                if (EPI >= 1) v += bias[col];
                if (EPI == 3) v += res[(size_t)row * N + col];
                if (EPI == 2) v = fmaxf(v, 0.0f);
                C[(size_t)row * N + col] = v;
            }
        }
    }
}

// ---------------------------------------------------------------------------
// Fused causal attention: one block per (head, batch), one thread per query.
// Online softmax, K/V staged through shared memory in 2 chunks of 64 keys.
// scale = C^-0.5 = 1/16 (reference scales by n_embd, not head_size!)
// ---------------------------------------------------------------------------
__global__ void __launch_bounds__(128)
attn_kernel(const float* __restrict__ q, const float* __restrict__ k,
            const float* __restrict__ v, float* __restrict__ out) {
    __shared__ __align__(16) float Ks[64 * HSn];
    __shared__ __align__(16) float Vs[64 * HSn];

    const int h  = blockIdx.x;
    const int b  = blockIdx.y;
    const int tq = threadIdx.x;                       // query index 0..127
    const size_t base = (size_t)(b * Tn) * Cn + h * HSn;

    float qr[HSn];
    #pragma unroll
    for (int d = 0; d < HSn; d += 4) {
        float4 t4 = *reinterpret_cast<const float4*>(&q[base + (size_t)tq * Cn + d]);
        qr[d] = t4.x; qr[d + 1] = t4.y; qr[d + 2] = t4.z; qr[d + 3] = t4.w;
    }

    float m = -1e30f, l = 0.0f;
    float acc[HSn];
    #pragma unroll
    for (int d = 0; d < HSn; d++) acc[d] = 0.0f;

    const int r    = tq >> 1;          // row this thread loads (0..63)
    const int half = (tq & 1) * 32;    // which 32-col half

    for (int ch = 0; ch < 2; ch++) {
        __syncthreads();   // previous chunk fully consumed before overwrite
        #pragma unroll
        for (int d = 0; d < 32; d += 4) {
            int col = half + d;
            size_t goff = base + (size_t)(ch * 64 + r) * Cn + col;
            *reinterpret_cast<float4*>(&Ks[r * HSn + col]) =
                *reinterpret_cast<const float4*>(&k[goff]);
            *reinterpret_cast<float4*>(&Vs[r * HSn + col]) =
                *reinterpret_cast<const float4*>(&v[goff]);
        }
        __syncthreads();

        int tmax = tq - ch * 64;                 // causal limit within chunk
        int lim  = tmax < 63 ? tmax : 63;
        for (int t = 0; t <= lim; t++) {         // skipped entirely if tmax<0
            float s = 0.0f;
            #pragma unroll
            for (int d = 0; d < HSn; d++) s = fmaf(qr[d], Ks[t * HSn + d], s);
            s *= 0.0625f;                        // 256^-0.5
            float mn   = fmaxf(m, s);
            float corr = __expf(m - mn);
            float p    = __expf(s - mn);
            l = l * corr + p;
            #pragma unroll
            for (int d = 0; d < HSn; d++)
                acc[d] = fmaf(acc[d], corr, p * Vs[t * HSn + d]);
            m = mn;
        }
    }

    float inv = 1.0f / l;
    #pragma unroll
    for (int d = 0; d < HSn; d++)
        out[base + (size_t)tq * Cn + d] = acc[d] * inv;
}

// ---------------------------------------------------------------------------
// Host driver (graph-capturable: kernel launches only)
// ---------------------------------------------------------------------------
extern "C" void kernel_launch(void* const* d_in, const int* in_sizes, int n_in,
                              void* d_out, int out_size) {
    const int*   idx     = (const int*)  d_in[0];
    const float* tok_emb = (const float*)d_in[1];
    const float* pos_emb = (const float*)d_in[2];
    const float* ln1_g   = (const float*)d_in[3];
    const float* ln1_b   = (const float*)d_in[4];
    const float* wq      = (const float*)d_in[5];
    const float* wk      = (const float*)d_in[6];
    const float* wv      = (const float*)d_in[7];
    const float* proj_w  = (const float*)d_in[8];
    const float* proj_b  = (const float*)d_in[9];
    const float* ln2_g   = (const float*)d_in[10];
    const float* ln2_b   = (const float*)d_in[11];
    const float* w1      = (const float*)d_in[12];
    const float* b1      = (const float*)d_in[13];
    const float* w2      = (const float*)d_in[14];
    const float* b2      = (const float*)d_in[15];
    const float* lnf_g   = (const float*)d_in[16];
    const float* lnf_b   = (const float*)d_in[17];
    const float* lm_w    = (const float*)d_in[18];
    const float* lm_b    = (const float*)d_in[19];
    float*       out     = (float*)d_out;

    float *x, *h, *qb, *kb, *vb, *att, *ffn;
    cudaGetSymbolAddress((void**)&x,   g_x);
    cudaGetSymbolAddress((void**)&h,   g_h);
    cudaGetSymbolAddress((void**)&qb,  g_q);
    cudaGetSymbolAddress((void**)&kb,  g_k);
    cudaGetSymbolAddress((void**)&vb,  g_v);
    cudaGetSymbolAddress((void**)&att, g_att);
    cudaGetSymbolAddress((void**)&ffn, g_ffn);

    embed_kernel<<<NTOK, Cn>>>(idx, tok_emb, pos_emb);

    dim3 gridC (Cn   / GBN,            NTOK / GBM);   // N=256
    dim3 gridF (DFFn / GBN,            NTOK / GBM);   // N=1024
    dim3 gridV ((Vn + GBN - 1) / GBN,  NTOK / GBM);   // N=10000
    dim3 gridA (Hn, Bn);

    for (int l = 0; l < Ln; l++) {
        const float* Wq = wq     + (size_t)l * Cn * Cn;
        const float* Wk = wk     + (size_t)l * Cn * Cn;
        const float* Wv = wv     + (size_t)l * Cn * Cn;
        const float* Wp = proj_w + (size_t)l * Cn * Cn;
        const float* W1 = w1     + (size_t)l * Cn * DFFn;
        const float* W2 = w2     + (size_t)l * DFFn * Cn;

        ln_kernel<<<NTOK, Cn>>>(x, ln1_g + l * Cn, ln1_b + l * Cn, h);

        sgemm_kernel<0><<<gridC, 256>>>(h, Wq, nullptr, nullptr, qb, NTOK, Cn, Cn);
        sgemm_kernel<0><<<gridC, 256>>>(h, Wk, nullptr, nullptr, kb, NTOK, Cn, Cn);
        sgemm_kernel<0><<<gridC, 256>>>(h, Wv, nullptr, nullptr, vb, NTOK, Cn, Cn);

        attn_kernel<<<gridA, 128>>>(qb, kb, vb, att);

        sgemm_kernel<3><<<gridC, 256>>>(att, Wp, proj_b + l * Cn, x, x,
                                        NTOK, Cn, Cn);

        ln_kernel<<<NTOK, Cn>>>(x, ln2_g + l * Cn, ln2_b + l * Cn, h);

        sgemm_kernel<2><<<gridF, 256>>>(h, W1, b1 + l * DFFn, nullptr, ffn,
                                        NTOK, DFFn, Cn);
        sgemm_kernel<3><<<gridC, 256>>>(ffn, W2, b2 + l * Cn, x, x,
                                        NTOK, Cn, DFFn);
    }

    ln_kernel<<<NTOK, Cn>>>(x, lnf_g, lnf_b, h);
    sgemm_kernel<1><<<gridV, 256>>>(h, lm_w, lm_b, nullptr, out,
                                    NTOK, Vn, Cn);
}

// round 4
// speedup vs baseline: 2.0491x; 2.0491x over previous
#include <cuda_runtime.h>
#include <cstdint>

// ---------------------------------------------------------------------------
// Problem constants
// ---------------------------------------------------------------------------
constexpr int Bn   = 128;
constexpr int Tn   = 128;
constexpr int Cn   = 256;
constexpr int Hn   = 4;
constexpr int Ln   = 6;
constexpr int Vn   = 10000;
constexpr int HSn  = 64;
constexpr int DFFn = 1024;
constexpr int NTOK = Bn * Tn;

// ---------------------------------------------------------------------------
// Scratch (device globals -- allocation-free per harness rules)
// ---------------------------------------------------------------------------
__device__ float g_x  [NTOK * Cn];
__device__ float g_h  [NTOK * Cn];
__device__ float g_q  [NTOK * Cn];
__device__ float g_k  [NTOK * Cn];
__device__ float g_v  [NTOK * Cn];
__device__ float g_att[NTOK * Cn];
__device__ float g_ffn[NTOK * DFFn];

// ---------------------------------------------------------------------------
// Embedding
// ---------------------------------------------------------------------------
__global__ void embed_kernel(const int* __restrict__ idx,
                             const float* __restrict__ tok,
                             const float* __restrict__ pos) {
    int token = blockIdx.x;
    int c     = threadIdx.x;
    int t     = token % Tn;
    int id    = idx[token];
    g_x[token * Cn + c] = tok[id * Cn + c] + pos[t * Cn + c];
}

// ---------------------------------------------------------------------------
// LayerNorm over C=256, one block per token
// ---------------------------------------------------------------------------
__global__ void ln_kernel(const float* __restrict__ in,
                          const float* __restrict__ gg,
                          const float* __restrict__ bb,
                          float* __restrict__ out) {
    __shared__ float red[Cn];
    int token = blockIdx.x;
    int c     = threadIdx.x;
    float v   = in[token * Cn + c];

    red[c] = v;
    __syncthreads();
    #pragma unroll
    for (int s = Cn / 2; s > 0; s >>= 1) {
        if (c < s) red[c] += red[c + s];
        __syncthreads();
    }
    float mean = red[0] * (1.0f / Cn);
    __syncthreads();

    float d = v - mean;
    red[c] = d * d;
    __syncthreads();
    #pragma unroll
    for (int s = Cn / 2; s > 0; s >>= 1) {
        if (c < s) red[c] += red[c + s];
        __syncthreads();
    }
    float var = red[0] * (1.0f / Cn);

    out[token * Cn + c] = d * rsqrtf(var + 1e-5f) * gg[c] + bb[c];
}

// ---------------------------------------------------------------------------
// TF32 tensor-core GEMM: C[M,N] = A[M,K] @ B[K,N] row-major, fused epilogues
//   EPI 0: plain   1: +bias   2: +bias,relu   3: +bias+residual
// Tile 128x128x32, 8 warps (2M x 4N), warp tile 64x32 (4x4 m16n8k8 atoms).
// Double-buffered smem, register-staged global loads, cvt.rna.tf32 on stage.
// ---------------------------------------------------------------------------
constexpr int TBM = 128;
constexpr int TBN = 128;
constexpr int TBK = 32;
constexpr int A_STRIDE = TBK + 4;   // 36 words  -> bank-conflict-free frags
constexpr int B_STRIDE = TBN + 8;   // 136 words -> bank-conflict-free frags
constexpr int A_BUF = TBM * A_STRIDE;         // 4608 words
constexpr int B_BUF = TBK * B_STRIDE;         // 4352 words
constexpr int SMEM_WORDS = 2 * A_BUF + 2 * B_BUF;   // 17920 words = 71680 B

__device__ __forceinline__ uint32_t f2tf32(float x) {
    uint32_t u;
    asm("cvt.rna.tf32.f32 %0, %1;" : "=r"(u) : "f"(x));
    return u;
}

__device__ __forceinline__ void mma_tf32(float c[4], const uint32_t a[4],
                                         const uint32_t b[2]) {
    asm volatile(
        "mma.sync.aligned.m16n8k8.row.col.f32.tf32.tf32.f32 "
        "{%0,%1,%2,%3}, {%4,%5,%6,%7}, {%8,%9}, {%0,%1,%2,%3};"
        : "+f"(c[0]), "+f"(c[1]), "+f"(c[2]), "+f"(c[3])
        : "r"(a[0]), "r"(a[1]), "r"(a[2]), "r"(a[3]), "r"(b[0]), "r"(b[1]));
}

template <int EPI>
__global__ void __launch_bounds__(256, 1)
tgemm_kernel(const float* __restrict__ A, const float* __restrict__ B,
             const float* __restrict__ bias, const float* __restrict__ res,
             float* __restrict__ C, int M, int N, int K) {
    extern __shared__ uint32_t smem[];
    uint32_t* AsBase = smem;
    uint32_t* BsBase = smem + 2 * A_BUF;

    const int tid  = threadIdx.x;
    const int warp = tid >> 5;
    const int lane = tid & 31;
    const int wm   = warp & 1;          // 0..1  (M)
    const int wn   = warp >> 1;         // 0..3  (N)
    const int grp  = lane >> 2;         // 0..7
    const int qid  = lane & 3;          // 0..3
    const int rowBase = blockIdx.y * TBM;
    const int colBase = blockIdx.x * TBN;

    float acc[4][4][4];
    #pragma unroll
    for (int i = 0; i < 4; i++)
        #pragma unroll
        for (int j = 0; j < 4; j++)
            #pragma unroll
            for (int r = 0; r < 4; r++) acc[i][j][r] = 0.0f;

    float4 ra[4], rb[4];
    const int ktiles = K / TBK;

    // ---- staging helpers
    auto ld_stage = [&](int kt) {
        #pragma unroll
        for (int it = 0; it < 4; it++) {
            int f  = tid + it * 256;
            int r  = f >> 3;
            int c4 = (f & 7) << 2;
            ra[it] = *reinterpret_cast<const float4*>(
                &A[(size_t)(rowBase + r) * K + kt * TBK + c4]);
        }
        #pragma unroll
        for (int it = 0; it < 4; it++) {
            int f  = tid + it * 256;
            int kr = f >> 5;
            int c4 = (f & 31) << 2;
            int gc = colBase + c4;
            if (gc < N) {   // N is always a multiple of 4; no straddle
                rb[it] = *reinterpret_cast<const float4*>(
                    &B[(size_t)(kt * TBK + kr) * N + gc]);
            } else {
                rb[it] = make_float4(0.f, 0.f, 0.f, 0.f);
            }
        }
    };
    auto st_stage = [&](int buf) {
        uint32_t* Ab = AsBase + buf * A_BUF;
        uint32_t* Bb = BsBase + buf * B_BUF;
        #pragma unroll
        for (int it = 0; it < 4; it++) {
            int f  = tid + it * 256;
            int r  = f >> 3;
            int c4 = (f & 7) << 2;
            uint4 v = {f2tf32(ra[it].x), f2tf32(ra[it].y),
                       f2tf32(ra[it].z), f2tf32(ra[it].w)};
            *reinterpret_cast<uint4*>(&Ab[r * A_STRIDE + c4]) = v;
        }
        #pragma unroll
        for (int it = 0; it < 4; it++) {
            int f  = tid + it * 256;
            int kr = f >> 5;
            int c4 = (f & 31) << 2;
            uint4 v = {f2tf32(rb[it].x), f2tf32(rb[it].y),
                       f2tf32(rb[it].z), f2tf32(rb[it].w)};
            *reinterpret_cast<uint4*>(&Bb[kr * B_STRIDE + c4]) = v;
        }
    };
    auto compute = [&](int buf) {
        uint32_t* Ab = AsBase + buf * A_BUF;
        uint32_t* Bb = BsBase + buf * B_BUF;
        #pragma unroll
        for (int ks = 0; ks < 4; ks++) {
            const int k0 = ks * 8;
            uint32_t af[4][4], bf[4][2];
            #pragma unroll
            for (int ma = 0; ma < 4; ma++) {
                int m0 = wm * 64 + ma * 16 + grp;
                af[ma][0] = Ab[m0 * A_STRIDE + k0 + qid];
                af[ma][1] = Ab[(m0 + 8) * A_STRIDE + k0 + qid];
                af[ma][2] = Ab[m0 * A_STRIDE + k0 + qid + 4];
                af[ma][3] = Ab[(m0 + 8) * A_STRIDE + k0 + qid + 4];
            }
            #pragma unroll
            for (int nb = 0; nb < 4; nb++) {
                int c = wn * 32 + nb * 8 + grp;
                bf[nb][0] = Bb[(k0 + qid) * B_STRIDE + c];
                bf[nb][1] = Bb[(k0 + qid + 4) * B_STRIDE + c];
            }
            #pragma unroll
            for (int ma = 0; ma < 4; ma++)
                #pragma unroll
                for (int nb = 0; nb < 4; nb++)
                    mma_tf32(acc[ma][nb], af[ma], bf[nb]);
        }
    };

    // ---- pipelined mainloop
    ld_stage(0);
    st_stage(0);
    __syncthreads();
    for (int kt = 0; kt < ktiles; kt++) {
        int buf = kt & 1;
        if (kt + 1 < ktiles) ld_stage(kt + 1);
        compute(buf);
        if (kt + 1 < ktiles) st_stage(buf ^ 1);
        __syncthreads();
    }

    // ---- epilogue
    #pragma unroll
    for (int ma = 0; ma < 4; ma++) {
        int row0 = rowBase + wm * 64 + ma * 16 + grp;
        #pragma unroll
        for (int nb = 0; nb < 4; nb++) {
            int col0 = colBase + wn * 32 + nb * 8 + qid * 2;
            #pragma unroll
            for (int half = 0; half < 2; half++) {    // c0/c1 then c2/c3
                int row = row0 + half * 8;
                #pragma unroll
                for (int j = 0; j < 2; j++) {
                    int col = col0 + j;
                    if (col < N) {
                        float v = acc[ma][nb][half * 2 + j];
                        if (EPI >= 1) v += bias[col];
                        if (EPI == 3) v += res[(size_t)row * N + col];
                        if (EPI == 2) v = fmaxf(v, 0.0f);
                        C[(size_t)row * N + col] = v;
                    }
                }
            }
        }
    }
}

// ---------------------------------------------------------------------------
// Fused causal attention (unchanged): one block per (head,batch),
// one thread per query, online softmax. scale = C^-0.5 = 1/16.
// ---------------------------------------------------------------------------
__global__ void __launch_bounds__(128)
attn_kernel(const float* __restrict__ q, const float* __restrict__ k,
            const float* __restrict__ v, float* __restrict__ out) {
    __shared__ __align__(16) float Ks[64 * HSn];
    __shared__ __align__(16) float Vs[64 * HSn];

    const int h  = blockIdx.x;
    const int b  = blockIdx.y;
    const int tq = threadIdx.x;
    const size_t base = (size_t)(b * Tn) * Cn + h * HSn;

    float qr[HSn];
    #pragma unroll
    for (int d = 0; d < HSn; d += 4) {
        float4 t4 = *reinterpret_cast<const float4*>(&q[base + (size_t)tq * Cn + d]);
        qr[d] = t4.x; qr[d + 1] = t4.y; qr[d + 2] = t4.z; qr[d + 3] = t4.w;
    }

    float m = -1e30f, l = 0.0f;
    float acc[HSn];
    #pragma unroll
    for (int d = 0; d < HSn; d++) acc[d] = 0.0f;

    const int r    = tq >> 1;
    const int half = (tq & 1) * 32;

    for (int ch = 0; ch < 2; ch++) {
        __syncthreads();
        #pragma unroll
        for (int d = 0; d < 32; d += 4) {
            int col = half + d;
            size_t goff = base + (size_t)(ch * 64 + r) * Cn + col;
            *reinterpret_cast<float4*>(&Ks[r * HSn + col]) =
                *reinterpret_cast<const float4*>(&k[goff]);
            *reinterpret_cast<float4*>(&Vs[r * HSn + col]) =
                *reinterpret_cast<const float4*>(&v[goff]);
        }
        __syncthreads();

        int tmax = tq - ch * 64;
        int lim  = tmax < 63 ? tmax : 63;
        for (int t = 0; t <= lim; t++) {
            float s = 0.0f;
            #pragma unroll
            for (int d = 0; d < HSn; d++) s = fmaf(qr[d], Ks[t * HSn + d], s);
            s *= 0.0625f;
            float mn   = fmaxf(m, s);
            float corr = __expf(m - mn);
            float p    = __expf(s - mn);
            l = l * corr + p;
            #pragma unroll
            for (int d = 0; d < HSn; d++)
                acc[d] = fmaf(acc[d], corr, p * Vs[t * HSn + d]);
            m = mn;
        }
    }

    float inv = 1.0f / l;
    #pragma unroll
    for (int d = 0; d < HSn; d++)
        out[base + (size_t)tq * Cn + d] = acc[d] * inv;
}

// ---------------------------------------------------------------------------
// Host driver (graph-capturable)
// ---------------------------------------------------------------------------
extern "C" void kernel_launch(void* const* d_in, const int* in_sizes, int n_in,
                              void* d_out, int out_size) {
    const int*   idx     = (const int*)  d_in[0];
    const float* tok_emb = (const float*)d_in[1];
    const float* pos_emb = (const float*)d_in[2];
    const float* ln1_g   = (const float*)d_in[3];
    const float* ln1_b   = (const float*)d_in[4];
    const float* wq      = (const float*)d_in[5];
    const float* wk      = (const float*)d_in[6];
    const float* wv      = (const float*)d_in[7];
    const float* proj_w  = (const float*)d_in[8];
    const float* proj_b  = (const float*)d_in[9];
    const float* ln2_g   = (const float*)d_in[10];
    const float* ln2_b   = (const float*)d_in[11];
    const float* w1      = (const float*)d_in[12];
    const float* b1      = (const float*)d_in[13];
    const float* w2      = (const float*)d_in[14];
    const float* b2      = (const float*)d_in[15];
    const float* lnf_g   = (const float*)d_in[16];
    const float* lnf_b   = (const float*)d_in[17];
    const float* lm_w    = (const float*)d_in[18];
    const float* lm_b    = (const float*)d_in[19];
    float*       out     = (float*)d_out;

    float *x, *h, *qb, *kb, *vb, *att, *ffn;
    cudaGetSymbolAddress((void**)&x,   g_x);
    cudaGetSymbolAddress((void**)&h,   g_h);
    cudaGetSymbolAddress((void**)&qb,  g_q);
    cudaGetSymbolAddress((void**)&kb,  g_k);
    cudaGetSymbolAddress((void**)&vb,  g_v);
    cudaGetSymbolAddress((void**)&att, g_att);
    cudaGetSymbolAddress((void**)&ffn, g_ffn);

    const int smemB = SMEM_WORDS * 4;   // 71680 bytes
    cudaFuncSetAttribute(tgemm_kernel<0>, cudaFuncAttributeMaxDynamicSharedMemorySize, smemB);
    cudaFuncSetAttribute(tgemm_kernel<1>, cudaFuncAttributeMaxDynamicSharedMemorySize, smemB);
    cudaFuncSetAttribute(tgemm_kernel<2>, cudaFuncAttributeMaxDynamicSharedMemorySize, smemB);
    cudaFuncSetAttribute(tgemm_kernel<3>, cudaFuncAttributeMaxDynamicSharedMemorySize, smemB);

    embed_kernel<<<NTOK, Cn>>>(idx, tok_emb, pos_emb);

    dim3 gridC (Cn   / TBN,                 NTOK / TBM);   // (2, 128)
    dim3 gridF (DFFn / TBN,                 NTOK / TBM);   // (8, 128)
    dim3 gridV ((Vn + TBN - 1) / TBN,       NTOK / TBM);   // (79, 128)
    dim3 gridA (Hn, Bn);

    for (int l = 0; l < Ln; l++) {
        const float* Wq = wq     + (size_t)l * Cn * Cn;
        const float* Wk = wk     + (size_t)l * Cn * Cn;
        const float* Wv = wv     + (size_t)l * Cn * Cn;
        const float* Wp = proj_w + (size_t)l * Cn * Cn;
        const float* W1 = w1     + (size_t)l * Cn * DFFn;
        const float* W2 = w2     + (size_t)l * DFFn * Cn;

        ln_kernel<<<NTOK, Cn>>>(x, ln1_g + l * Cn, ln1_b + l * Cn, h);

        tgemm_kernel<0><<<gridC, 256, smemB>>>(h, Wq, nullptr, nullptr, qb, NTOK, Cn, Cn);
        tgemm_kernel<0><<<gridC, 256, smemB>>>(h, Wk, nullptr, nullptr, kb, NTOK, Cn, Cn);
        tgemm_kernel<0><<<gridC, 256, smemB>>>(h, Wv, nullptr, nullptr, vb, NTOK, Cn, Cn);

        attn_kernel<<<gridA, 128>>>(qb, kb, vb, att);

        tgemm_kernel<3><<<gridC, 256, smemB>>>(att, Wp, proj_b + l * Cn, x, x,
                                               NTOK, Cn, Cn);

        ln_kernel<<<NTOK, Cn>>>(x, ln2_g + l * Cn, ln2_b + l * Cn, h);

        tgemm_kernel<2><<<gridF, 256, smemB>>>(h, W1, b1 + l * DFFn, nullptr, ffn,
                                               NTOK, DFFn, Cn);
        tgemm_kernel<3><<<gridC, 256, smemB>>>(ffn, W2, b2 + l * Cn, x, x,
                                               NTOK, Cn, DFFn);
    }

    ln_kernel<<<NTOK, Cn>>>(x, lnf_g, lnf_b, h);
    tgemm_kernel<1><<<gridV, 256, smemB>>>(h, lm_w, lm_b, nullptr, out,
                                           NTOK, Vn, Cn);
}

// round 5
// speedup vs baseline: 2.2880x; 1.1166x over previous
#include <cuda_runtime.h>
#include <cstdint>

// ---------------------------------------------------------------------------
// Problem constants
// ---------------------------------------------------------------------------
constexpr int Bn   = 128;
constexpr int Tn   = 128;
constexpr int Cn   = 256;
constexpr int Hn   = 4;
constexpr int Ln   = 6;
constexpr int Vn   = 10000;
constexpr int HSn  = 64;
constexpr int DFFn = 1024;
constexpr int NTOK = Bn * Tn;
constexpr int QKVN = 3 * Cn;       // 768

// ---------------------------------------------------------------------------
// Scratch (device globals -- allocation-free per harness rules)
// ---------------------------------------------------------------------------
__device__ float g_x   [NTOK * Cn];
__device__ float g_h   [NTOK * Cn];
__device__ float g_qkv [NTOK * QKVN];
__device__ float g_att [NTOK * Cn];
__device__ float g_ffn [NTOK * DFFn];
// tf32-rounded weight copies
__device__ float g_qkvw[Ln * Cn * QKVN];
__device__ float g_projw[Ln * Cn * Cn];
__device__ float g_w1  [Ln * Cn * DFFn];
__device__ float g_w2  [Ln * DFFn * Cn];
__device__ float g_lmw [Cn * Vn];

__device__ __forceinline__ uint32_t f2tf32(float x) {
    uint32_t u;
    asm("cvt.rna.tf32.f32 %0, %1;" : "=r"(u) : "f"(x));
    return u;
}

// ---------------------------------------------------------------------------
// Weight pre-rounding (runs once per launch; ~30MB traffic, negligible)
// ---------------------------------------------------------------------------
__global__ void round_copy_kernel(const float* __restrict__ src,
                                  float* __restrict__ dst, int n4) {
    int i = blockIdx.x * blockDim.x + threadIdx.x;
    if (i < n4) {
        float4 v = reinterpret_cast<const float4*>(src)[i];
        uint4  u = {f2tf32(v.x), f2tf32(v.y), f2tf32(v.z), f2tf32(v.w)};
        reinterpret_cast<uint4*>(dst)[i] = u;
    }
}

// pack wq|wk|wv -> [L][C][768], tf32-rounded
__global__ void pack_qkv_kernel(const float* __restrict__ wq,
                                const float* __restrict__ wk,
                                const float* __restrict__ wv,
                                float* __restrict__ dst) {
    int i = blockIdx.x * blockDim.x + threadIdx.x;   // float4 index in [L*C][64]
    const int total = Ln * Cn * (Cn / 4);
    if (i < total) {
        int lc = i / (Cn / 4);
        int j4 = i % (Cn / 4);
        uint4* d = reinterpret_cast<uint4*>(dst) + (size_t)lc * (QKVN / 4);
        float4 a = reinterpret_cast<const float4*>(wq)[i];
        float4 b = reinterpret_cast<const float4*>(wk)[i];
        float4 c = reinterpret_cast<const float4*>(wv)[i];
        d[j4]                = {f2tf32(a.x), f2tf32(a.y), f2tf32(a.z), f2tf32(a.w)};
        d[j4 + Cn / 4]       = {f2tf32(b.x), f2tf32(b.y), f2tf32(b.z), f2tf32(b.w)};
        d[j4 + 2 * (Cn / 4)] = {f2tf32(c.x), f2tf32(c.y), f2tf32(c.z), f2tf32(c.w)};
    }
}

// ---------------------------------------------------------------------------
// Embedding
// ---------------------------------------------------------------------------
__global__ void embed_kernel(const int* __restrict__ idx,
                             const float* __restrict__ tok,
                             const float* __restrict__ pos) {
    int token = blockIdx.x;
    int c     = threadIdx.x;
    int t     = token % Tn;
    int id    = idx[token];
    g_x[token * Cn + c] = tok[id * Cn + c] + pos[t * Cn + c];
}

// ---------------------------------------------------------------------------
// LayerNorm (shuffle reductions), output tf32-rounded (feeds GEMM A operand)
// ---------------------------------------------------------------------------
__global__ void __launch_bounds__(Cn)
ln_kernel(const float* __restrict__ in, const float* __restrict__ gg,
          const float* __restrict__ bb, float* __restrict__ out) {
    __shared__ float part[8];
    int token = blockIdx.x;
    int c     = threadIdx.x;
    int lane  = c & 31, w = c >> 5;
    float v = in[token * Cn + c];

    float s = v;
    #pragma unroll
    for (int o = 16; o; o >>= 1) s += __shfl_xor_sync(~0u, s, o);
    if (!lane) part[w] = s;
    __syncthreads();
    float tot = 0.f;
    #pragma unroll
    for (int i = 0; i < 8; i++) tot += part[i];
    float mean = tot * (1.0f / Cn);
    float d = v - mean;
    __syncthreads();

    s = d * d;
    #pragma unroll
    for (int o = 16; o; o >>= 1) s += __shfl_xor_sync(~0u, s, o);
    if (!lane) part[w] = s;
    __syncthreads();
    tot = 0.f;
    #pragma unroll
    for (int i = 0; i < 8; i++) tot += part[i];
    float var = tot * (1.0f / Cn);

    float r = d * rsqrtf(var + 1e-5f) * gg[c] + bb[c];
    out[token * Cn + c] = __uint_as_float(f2tf32(r));
}

// ---------------------------------------------------------------------------
// TF32 tensor-core GEMM, cp.async 3-stage pipeline.
// Operands must be pre-rounded to tf32 (bits passed raw to mma).
//   EPI 0: plain   1: +bias   2: +bias,relu,tf32-round   3: +bias+residual
// Tile 128x128x32, 8 warps (2M x 4N), warp tile 64x32 (4x4 m16n8k8 atoms).
// ---------------------------------------------------------------------------
constexpr int TBM = 128;
constexpr int TBN = 128;
constexpr int TBK = 32;
constexpr int A_STRIDE = TBK + 4;                 // 36 words
constexpr int B_STRIDE = TBN + 8;                 // 136 words
constexpr int A_BUF = TBM * A_STRIDE;             // 4608 words
constexpr int B_BUF = TBK * B_STRIDE;             // 4352 words
constexpr int STAGE_WORDS = A_BUF + B_BUF;        // 8960 words
constexpr int STAGES = 3;
constexpr int GEMM_SMEM_B = STAGES * STAGE_WORDS * 4;   // 107520 bytes

__device__ __forceinline__ void cp_async16(uint32_t daddr, const void* gptr,
                                           bool pred) {
    int sz = pred ? 16 : 0;
    asm volatile("cp.async.cg.shared.global [%0], [%1], 16, %2;\n"
                 :: "r"(daddr), "l"(gptr), "r"(sz));
}
__device__ __forceinline__ void cp_commit() {
    asm volatile("cp.async.commit_group;\n" ::: "memory");
}
template <int N>
__device__ __forceinline__ void cp_wait() {
    asm volatile("cp.async.wait_group %0;\n" :: "n"(N) : "memory");
}

__device__ __forceinline__ void mma_tf32(float c[4], const uint32_t a[4],
                                         const uint32_t b[2]) {
    asm volatile(
        "mma.sync.aligned.m16n8k8.row.col.f32.tf32.tf32.f32 "
        "{%0,%1,%2,%3}, {%4,%5,%6,%7}, {%8,%9}, {%0,%1,%2,%3};"
        : "+f"(c[0]), "+f"(c[1]), "+f"(c[2]), "+f"(c[3])
        : "r"(a[0]), "r"(a[1]), "r"(a[2]), "r"(a[3]), "r"(b[0]), "r"(b[1]));
}

template <int EPI>
__global__ void __launch_bounds__(256, 1)
tgemm_kernel(const float* __restrict__ A, const float* __restrict__ B,
             const float* __restrict__ bias, const float* __restrict__ res,
             float* __restrict__ C, int M, int N, int K) {
    extern __shared__ float smem[];
    const uint32_t smem_u32 = (uint32_t)__cvta_generic_to_shared(smem);

    const int tid  = threadIdx.x;
    const int warp = tid >> 5;
    const int lane = tid & 31;
    const int wm   = warp & 1;
    const int wn   = warp >> 1;
    const int grp  = lane >> 2;
    const int qid  = lane & 3;
    const int rowBase = blockIdx.y * TBM;
    const int colBase = blockIdx.x * TBN;

    // per-thread copy coordinates (fixed across k-tiles)
    int a_r[4], a_c[4], b_kr[4], b_c[4];
    bool b_ok[4];
    #pragma unroll
    for (int it = 0; it < 4; it++) {
        int f = tid + it * 256;
        a_r[it] = f >> 3;               // 0..127
        a_c[it] = (f & 7) << 2;         // 0,4,..,28
        b_kr[it] = f >> 5;              // 0..31
        b_c[it]  = (f & 31) << 2;       // 0,4,..,124
        b_ok[it] = (colBase + b_c[it]) < N;   // N % 4 == 0, no straddle
    }

    auto issue = [&](int kt, int stage) {
        uint32_t sa = smem_u32 + (stage * STAGE_WORDS) * 4;
        uint32_t sb = sa + A_BUF * 4;
        #pragma unroll
        for (int it = 0; it < 4; it++) {
            const float* g = &A[(size_t)(rowBase + a_r[it]) * K + kt * TBK + a_c[it]];
            cp_async16(sa + (a_r[it] * A_STRIDE + a_c[it]) * 4, g, true);
        }
        #pragma unroll
        for (int it = 0; it < 4; it++) {
            const float* g = &B[(size_t)(kt * TBK + b_kr[it]) * N + colBase + b_c[it]];
            cp_async16(sb + (b_kr[it] * B_STRIDE + b_c[it]) * 4, g, b_ok[it]);
        }
        cp_commit();
    };

    float acc[4][4][4];
    #pragma unroll
    for (int i = 0; i < 4; i++)
        #pragma unroll
        for (int j = 0; j < 4; j++)
            #pragma unroll
            for (int r = 0; r < 4; r++) acc[i][j][r] = 0.0f;

    auto compute = [&](int stage) {
        const uint32_t* Ab = reinterpret_cast<const uint32_t*>(smem)
                             + stage * STAGE_WORDS;
        const uint32_t* Bb = Ab + A_BUF;
        #pragma unroll
        for (int ks = 0; ks < 4; ks++) {
            const int k0 = ks * 8;
            uint32_t af[4][4], bf[4][2];
            #pragma unroll
            for (int ma = 0; ma < 4; ma++) {
                int m0 = wm * 64 + ma * 16 + grp;
                af[ma][0] = Ab[m0 * A_STRIDE + k0 + qid];
                af[ma][1] = Ab[(m0 + 8) * A_STRIDE + k0 + qid];
                af[ma][2] = Ab[m0 * A_STRIDE + k0 + qid + 4];
                af[ma][3] = Ab[(m0 + 8) * A_STRIDE + k0 + qid + 4];
            }
            #pragma unroll
            for (int nb = 0; nb < 4; nb++) {
                int cc = wn * 32 + nb * 8 + grp;
                bf[nb][0] = Bb[(k0 + qid) * B_STRIDE + cc];
                bf[nb][1] = Bb[(k0 + qid + 4) * B_STRIDE + cc];
            }
            #pragma unroll
            for (int ma = 0; ma < 4; ma++)
                #pragma unroll
                for (int nb = 0; nb < 4; nb++)
                    mma_tf32(acc[ma][nb], af[ma], bf[nb]);
        }
    };

    const int ktiles = K / TBK;
    issue(0, 0);
    if (ktiles > 1) issue(1, 1); else cp_commit();

    for (int kt = 0; kt < ktiles; kt++) {
        int stage = kt % STAGES;
        cp_wait<1>();
        __syncthreads();
        int nk = kt + 2;
        if (nk < ktiles) issue(nk, nk % STAGES); else cp_commit();
        compute(stage);
        __syncthreads();
    }

    // ---- epilogue
    #pragma unroll
    for (int ma = 0; ma < 4; ma++) {
        int row0 = rowBase + wm * 64 + ma * 16 + grp;
        #pragma unroll
        for (int nb = 0; nb < 4; nb++) {
            int col0 = colBase + wn * 32 + nb * 8 + qid * 2;
            #pragma unroll
            for (int half = 0; half < 2; half++) {
                int row = row0 + half * 8;
                #pragma unroll
                for (int j = 0; j < 2; j++) {
                    int col = col0 + j;
                    if (col < N) {
                        float v = acc[ma][nb][half * 2 + j];
                        if (EPI >= 1) v += bias[col];
                        if (EPI == 3) v += res[(size_t)row * N + col];
                        if (EPI == 2) {
                            v = fmaxf(v, 0.0f);
                            v = __uint_as_float(f2tf32(v));   // feeds next GEMM
                        }
                        C[(size_t)row * N + col] = v;
                    }
                }
            }
        }
    }
}

// ---------------------------------------------------------------------------
// Fused causal attention on packed qkv [NTOK][768].
// One block per (head,batch), one thread per query, online softmax.
// scale = C^-0.5 = 1/16. Output tf32-rounded (feeds proj GEMM).
// ---------------------------------------------------------------------------
__global__ void __launch_bounds__(128)
attn_kernel(const float* __restrict__ qkv, float* __restrict__ out) {
    __shared__ __align__(16) float Ks[64 * HSn];
    __shared__ __align__(16) float Vs[64 * HSn];

    const int h  = blockIdx.x;
    const int b  = blockIdx.y;
    const int tq = threadIdx.x;
    const int token = b * Tn + tq;

    float qr[HSn];
    #pragma unroll
    for (int d = 0; d < HSn; d += 4) {
        float4 t4 = *reinterpret_cast<const float4*>(
            &qkv[(size_t)token * QKVN + h * HSn + d]);
        qr[d] = t4.x; qr[d + 1] = t4.y; qr[d + 2] = t4.z; qr[d + 3] = t4.w;
    }

    float m = -1e30f, l = 0.0f;
    float acc[HSn];
    #pragma unroll
    for (int d = 0; d < HSn; d++) acc[d] = 0.0f;

    const int r    = tq >> 1;
    const int half = (tq & 1) * 32;

    for (int ch = 0; ch < 2; ch++) {
        __syncthreads();
        int tok2 = b * Tn + ch * 64 + r;
        #pragma unroll
        for (int d = 0; d < 32; d += 4) {
            int col = half + d;
            *reinterpret_cast<float4*>(&Ks[r * HSn + col]) =
                *reinterpret_cast<const float4*>(
                    &qkv[(size_t)tok2 * QKVN + Cn + h * HSn + col]);
            *reinterpret_cast<float4*>(&Vs[r * HSn + col]) =
                *reinterpret_cast<const float4*>(
                    &qkv[(size_t)tok2 * QKVN + 2 * Cn + h * HSn + col]);
        }
        __syncthreads();

        int tmax = tq - ch * 64;
        int lim  = tmax < 63 ? tmax : 63;
        for (int t = 0; t <= lim; t++) {
            float s = 0.0f;
            #pragma unroll
            for (int d = 0; d < HSn; d++) s = fmaf(qr[d], Ks[t * HSn + d], s);
            s *= 0.0625f;
            float mn   = fmaxf(m, s);
            float corr = __expf(m - mn);
            float p    = __expf(s - mn);
            l = l * corr + p;
            #pragma unroll
            for (int d = 0; d < HSn; d++)
                acc[d] = fmaf(acc[d], corr, p * Vs[t * HSn + d]);
            m = mn;
        }
    }

    float inv = 1.0f / l;
    #pragma unroll
    for (int d = 0; d < HSn; d++)
        out[(size_t)token * Cn + h * HSn + d] =
            __uint_as_float(f2tf32(acc[d] * inv));
}

// ---------------------------------------------------------------------------
// Host driver (graph-capturable)
// ---------------------------------------------------------------------------
extern "C" void kernel_launch(void* const* d_in, const int* in_sizes, int n_in,
                              void* d_out, int out_size) {
    const int*   idx     = (const int*)  d_in[0];
    const float* tok_emb = (const float*)d_in[1];
    const float* pos_emb = (const float*)d_in[2];
    const float* ln1_g   = (const float*)d_in[3];
    const float* ln1_b   = (const float*)d_in[4];
    const float* wq      = (const float*)d_in[5];
    const float* wk      = (const float*)d_in[6];
    const float* wv      = (const float*)d_in[7];
    const float* proj_w  = (const float*)d_in[8];
    const float* proj_b  = (const float*)d_in[9];
    const float* ln2_g   = (const float*)d_in[10];
    const float* ln2_b   = (const float*)d_in[11];
    const float* w1      = (const float*)d_in[12];
    const float* b1      = (const float*)d_in[13];
    const float* w2      = (const float*)d_in[14];
    const float* b2      = (const float*)d_in[15];
    const float* lnf_g   = (const float*)d_in[16];
    const float* lnf_b   = (const float*)d_in[17];
    const float* lm_w    = (const float*)d_in[18];
    const float* lm_b    = (const float*)d_in[19];
    float*       out     = (float*)d_out;

    float *x, *h, *qkvb, *att, *ffn, *qkvw, *projw, *w1r, *w2r, *lmw;
    cudaGetSymbolAddress((void**)&x,     g_x);
    cudaGetSymbolAddress((void**)&h,     g_h);
    cudaGetSymbolAddress((void**)&qkvb,  g_qkv);
    cudaGetSymbolAddress((void**)&att,   g_att);
    cudaGetSymbolAddress((void**)&ffn,   g_ffn);
    cudaGetSymbolAddress((void**)&qkvw,  g_qkvw);
    cudaGetSymbolAddress((void**)&projw, g_projw);
    cudaGetSymbolAddress((void**)&w1r,   g_w1);
    cudaGetSymbolAddress((void**)&w2r,   g_w2);
    cudaGetSymbolAddress((void**)&lmw,   g_lmw);

    cudaFuncSetAttribute(tgemm_kernel<0>, cudaFuncAttributeMaxDynamicSharedMemorySize, GEMM_SMEM_B);
    cudaFuncSetAttribute(tgemm_kernel<1>, cudaFuncAttributeMaxDynamicSharedMemorySize, GEMM_SMEM_B);
    cudaFuncSetAttribute(tgemm_kernel<2>, cudaFuncAttributeMaxDynamicSharedMemorySize, GEMM_SMEM_B);
    cudaFuncSetAttribute(tgemm_kernel<3>, cudaFuncAttributeMaxDynamicSharedMemorySize, GEMM_SMEM_B);

    // --- weight pre-rounding
    {
        int n4;
        n4 = Ln * Cn * (Cn / 4);
        pack_qkv_kernel<<<(n4 + 255) / 256, 256>>>(wq, wk, wv, qkvw);
        n4 = Ln * Cn * Cn / 4;
        round_copy_kernel<<<(n4 + 255) / 256, 256>>>(proj_w, projw, n4);
        n4 = Ln * Cn * DFFn / 4;
        round_copy_kernel<<<(n4 + 255) / 256, 256>>>(w1, w1r, n4);
        round_copy_kernel<<<(n4 + 255) / 256, 256>>>(w2, w2r, n4);
        n4 = Cn * Vn / 4;
        round_copy_kernel<<<(n4 + 255) / 256, 256>>>(lm_w, lmw, n4);
    }

    embed_kernel<<<NTOK, Cn>>>(idx, tok_emb, pos_emb);

    dim3 gridQKV(QKVN / TBN,           NTOK / TBM);   // (6, 128)
    dim3 gridC  (Cn / TBN,             NTOK / TBM);   // (2, 128)
    dim3 gridF  (DFFn / TBN,           NTOK / TBM);   // (8, 128)
    dim3 gridV  ((Vn + TBN - 1) / TBN, NTOK / TBM);   // (79, 128)
    dim3 gridA  (Hn, Bn);

    for (int l = 0; l < Ln; l++) {
        const float* Wqkv = qkvw  + (size_t)l * Cn * QKVN;
        const float* Wp   = projw + (size_t)l * Cn * Cn;
        const float* W1   = w1r   + (size_t)l * Cn * DFFn;
        const float* W2   = w2r   + (size_t)l * DFFn * Cn;

        ln_kernel<<<NTOK, Cn>>>(x, ln1_g + l * Cn, ln1_b + l * Cn, h);

        tgemm_kernel<0><<<gridQKV, 256, GEMM_SMEM_B>>>(h, Wqkv, nullptr, nullptr,
                                                       qkvb, NTOK, QKVN, Cn);

        attn_kernel<<<gridA, 128>>>(qkvb, att);

        tgemm_kernel<3><<<gridC, 256, GEMM_SMEM_B>>>(att, Wp, proj_b + l * Cn, x, x,
                                                     NTOK, Cn, Cn);

        ln_kernel<<<NTOK, Cn>>>(x, ln2_g + l * Cn, ln2_b + l * Cn, h);

        tgemm_kernel<2><<<gridF, 256, GEMM_SMEM_B>>>(h, W1, b1 + l * DFFn, nullptr,
                                                     ffn, NTOK, DFFn, Cn);
        tgemm_kernel<3><<<gridC, 256, GEMM_SMEM_B>>>(ffn, W2, b2 + l * Cn, x, x,
                                                     NTOK, Cn, DFFn);
    }

    ln_kernel<<<NTOK, Cn>>>(x, lnf_g, lnf_b, h);
    tgemm_kernel<1><<<gridV, 256, GEMM_SMEM_B>>>(h, lmw, lm_b, nullptr, out,
                                                 NTOK, Vn, Cn);
}